// round 5
// baseline (speedup 1.0000x reference)
#include <cuda_runtime.h>

// Screen geometry (must match reference exactly, as float32)
#define NX 1024
#define NY 1024
__device__ __constant__ float c_LEFT   = -0.00512f;
__device__ __constant__ float c_RIGHT  =  0.00512f;
__device__ __constant__ float c_BOTTOM = -0.00512f;
__device__ __constant__ float c_TOP    =  0.00512f;
__device__ __constant__ float c_HSTEP  =  1e-5f;
__device__ __constant__ float c_VSTEP  =  1e-5f;

#define N_PARTICLES 16777216
#define TPB 256
#define NZERO 256               // zeroer blocks; < guaranteed wave-1 residency (~444)
#define IMG_F4 (NX * NY / 4)    // 262144 float4s = 4 MB

// Cross-block coordination state (reset by the last block each run -> replay-safe)
__device__ unsigned g_zero_done   = 0;
__device__ unsigned g_blocks_done = 0;

__device__ __forceinline__ void deposit(float x, float y, float* __restrict__ out) {
    // Match jnp.floor((x - LEFT)/HSTEP) in fp32 with IEEE round-to-nearest division.
    bool valid = (x >= c_LEFT) & (x <= c_RIGHT) & (y >= c_BOTTOM) & (y <= c_TOP);
    int ix = (int)floorf(__fdiv_rn(x - c_LEFT,   c_HSTEP));
    int iy = (int)floorf(__fdiv_rn(y - c_BOTTOM, c_VSTEP));
    if (x == c_RIGHT) ix = NX - 1;
    if (y == c_TOP)   iy = NY - 1;
    ix = min(max(ix, 0), NX - 1);
    iy = min(max(iy, 0), NY - 1);
    int flat = (NY - 1 - iy) * NX + ix;
    if (valid) atomicAdd(out + flat, 1.0f);  // fire-and-forget -> RED.E.ADD.F32
}

__global__ void __launch_bounds__(TPB)
hist_fused_kernel(const float4* __restrict__ xs4, const float4* __restrict__ ys4,
                  const float* __restrict__ mis, float* __restrict__ out) {
    int bid = blockIdx.x;

    // ---- Phase 1: first NZERO blocks zero the 4 MB image ----
    if (bid < NZERO) {
        float4* o4 = (float4*)out;
        int base = bid * (IMG_F4 / NZERO) + threadIdx.x;   // 1024 f4 per block
#pragma unroll
        for (int j = 0; j < (IMG_F4 / NZERO) / TPB; j++)   // 4 per thread
            o4[base + j * TPB] = make_float4(0.f, 0.f, 0.f, 0.f);
        __syncthreads();
        if (threadIdx.x == 0) {
            __threadfence();                  // stores visible before flag
            atomicAdd(&g_zero_done, 1u);
        }
    }

    // ---- Barrier: wait until the whole image is zeroed ----
    if (threadIdx.x == 0) {
        volatile unsigned* p = &g_zero_done;
        while (*p < NZERO) { }
        __threadfence();                      // acquire
    }
    __syncthreads();

    // ---- Phase 2: deposit 4 particles per thread ----
    int i = bid * TPB + threadIdx.x;
    float mx = __ldg(mis);
    float my = __ldg(mis + 1);
    float4 x4 = xs4[i];
    float4 y4 = ys4[i];
    deposit(x4.x - mx, y4.x - my, out);
    deposit(x4.y - mx, y4.y - my, out);
    deposit(x4.z - mx, y4.z - my, out);
    deposit(x4.w - mx, y4.w - my, out);

    // ---- Epilogue: last block resets flags so graph replay starts clean ----
    __syncthreads();
    if (threadIdx.x == 0) {
        __threadfence();
        unsigned d = atomicAdd(&g_blocks_done, 1u);
        if (d == gridDim.x - 1) {
            g_zero_done   = 0;
            g_blocks_done = 0;
            __threadfence();
        }
    }
}

extern "C" void kernel_launch(void* const* d_in, const int* in_sizes, int n_in,
                              void* d_out, int out_size) {
    const float* xs  = (const float*)d_in[0];
    const float* ys  = (const float*)d_in[1];
    const float* mis = (const float*)d_in[2];
    float* out = (float*)d_out;

    int work = N_PARTICLES / 4;              // 4,194,304 threads, 4 particles each
    hist_fused_kernel<<<work / TPB, TPB>>>((const float4*)xs, (const float4*)ys,
                                           mis, out);
}

// round 6
// speedup vs baseline: 1.3526x; 1.3526x over previous
#include <cuda_runtime.h>

#define NX 1024
#define NY 1024
__device__ __constant__ float c_LEFT   = -0.00512f;
__device__ __constant__ float c_RIGHT  =  0.00512f;
__device__ __constant__ float c_BOTTOM = -0.00512f;
__device__ __constant__ float c_TOP    =  0.00512f;
__device__ __constant__ float c_HSTEP  =  1e-5f;
__device__ __constant__ float c_VSTEP  =  1e-5f;

#define N_PARTICLES 16777216
#define N_F4        (N_PARTICLES / 4)     // 4,194,304
#define IMG_F4      (NX * NY / 4)         // 262,144
#define GRID        148                   // one CTA per SM: single wave, barrier-safe
#define BDIM        512

#define WIN_W 224
#define WIN_H 224
#define WIN_BINS (WIN_W * WIN_H)          // 50,176 u32 = 200,704 B smem

__device__ unsigned g_zero_arrived = 0;   // fused-zero barrier
__device__ unsigned g_blocks_done  = 0;   // replay-safe reset

__global__ void __launch_bounds__(BDIM, 1)
hist_priv_kernel(const float4* __restrict__ xs4, const float4* __restrict__ ys4,
                 const float* __restrict__ mis, float* __restrict__ out) {
    extern __shared__ unsigned sh[];      // WIN_BINS counters
    const int tid = threadIdx.x;
    const int bid = blockIdx.x;

    // ---- Zero private smem histogram ----
    for (int b = tid; b < WIN_BINS; b += BDIM) sh[b] = 0u;

    // ---- Fused zero of the 4 MB global image (each block a stripe) ----
    {
        float4* o4 = (float4*)out;
        const int per = (IMG_F4 + GRID - 1) / GRID;       // 1772
        int lo = bid * per;
        int hi = min(lo + per, IMG_F4);
        for (int i = lo + tid; i < hi; i += BDIM)
            o4[i] = make_float4(0.f, 0.f, 0.f, 0.f);
    }
    __syncthreads();
    if (tid == 0) {
        __threadfence();
        atomicAdd(&g_zero_arrived, 1u);
        volatile unsigned* p = &g_zero_arrived;
        while (*p < GRID) { }
        __threadfence();
    }
    __syncthreads();

    // ---- Window origin from beam center (general in misalignment) ----
    const float mx = __ldg(mis);
    const float my = __ldg(mis + 1);
    int cx = (int)floorf(__fdiv_rn(-mx - c_LEFT,   c_HSTEP));
    int cy = (int)floorf(__fdiv_rn(-my - c_BOTTOM, c_VSTEP));
    const int ox = min(max(cx - WIN_W / 2, 0), NX - WIN_W);
    const int oy = min(max(cy - WIN_H / 2, 0), NY - WIN_H);

    // ---- Deposit: smem for the hot window, global RED otherwise ----
    for (int i = bid * BDIM + tid; i < N_F4; i += GRID * BDIM) {
        float4 x4 = xs4[i];
        float4 y4 = ys4[i];
        float px[4] = {x4.x - mx, x4.y - mx, x4.z - mx, x4.w - mx};
        float py[4] = {y4.x - my, y4.y - my, y4.z - my, y4.w - my};
#pragma unroll
        for (int k = 0; k < 4; k++) {
            float x = px[k], y = py[k];
            bool valid = (x >= c_LEFT) & (x <= c_RIGHT) & (y >= c_BOTTOM) & (y <= c_TOP);
            int ix = (int)floorf(__fdiv_rn(x - c_LEFT,   c_HSTEP));
            int iy = (int)floorf(__fdiv_rn(y - c_BOTTOM, c_VSTEP));
            if (x == c_RIGHT) ix = NX - 1;
            if (y == c_TOP)   iy = NY - 1;
            ix = min(max(ix, 0), NX - 1);
            iy = min(max(iy, 0), NY - 1);
            if (valid) {
                int wx = ix - ox, wy = iy - oy;
                if ((unsigned)wx < WIN_W && (unsigned)wy < WIN_H) {
                    atomicAdd(&sh[wy * WIN_W + wx], 1u);          // ATOMS (smem pipe)
                } else {
                    atomicAdd(out + (NY - 1 - iy) * NX + ix, 1.0f); // scattered REDG
                }
            }
        }
    }
    __syncthreads();

    // ---- Flush window: coalesced REDs (consecutive bins -> consecutive gmem) ----
    for (int b = tid; b < WIN_BINS; b += BDIM) {
        unsigned v = sh[b];
        if (v) {
            int wy = b / WIN_W, wx = b - wy * WIN_W;
            atomicAdd(out + (NY - 1 - (oy + wy)) * NX + (ox + wx), (float)v);
        }
    }

    // ---- Replay-safe reset of barrier counters ----
    __syncthreads();
    if (tid == 0) {
        __threadfence();
        unsigned d = atomicAdd(&g_blocks_done, 1u);
        if (d == GRID - 1) {
            g_zero_arrived = 0;
            g_blocks_done  = 0;
            __threadfence();
        }
    }
}

extern "C" void kernel_launch(void* const* d_in, const int* in_sizes, int n_in,
                              void* d_out, int out_size) {
    const float* xs  = (const float*)d_in[0];
    const float* ys  = (const float*)d_in[1];
    const float* mis = (const float*)d_in[2];
    float* out = (float*)d_out;

    const size_t shmem = WIN_BINS * sizeof(unsigned);   // 200,704 B
    cudaFuncSetAttribute(hist_priv_kernel,
                         cudaFuncAttributeMaxDynamicSharedMemorySize, (int)shmem);

    hist_priv_kernel<<<GRID, BDIM, shmem>>>((const float4*)xs, (const float4*)ys,
                                            mis, out);
}

// round 7
// speedup vs baseline: 1.5852x; 1.1719x over previous
#include <cuda_runtime.h>

// Screen geometry (must match reference exactly, as float32)
#define NX 1024
#define NY 1024
__device__ __constant__ float c_LEFT   = -0.00512f;
__device__ __constant__ float c_RIGHT  =  0.00512f;
__device__ __constant__ float c_BOTTOM = -0.00512f;
__device__ __constant__ float c_TOP    =  0.00512f;
__device__ __constant__ float c_HSTEP  =  1e-5f;
__device__ __constant__ float c_VSTEP  =  1e-5f;

#define N_PARTICLES 16777216
#define TPB 256

__global__ void zero_out_kernel(float4* __restrict__ out, int n4) {
    int i = blockIdx.x * blockDim.x + threadIdx.x;
    if (i < n4) out[i] = make_float4(0.f, 0.f, 0.f, 0.f);
    // Let the dependent (hist) grid begin launching now; its
    // cudaGridDependencySynchronize() still waits for our stores to land.
    cudaTriggerProgrammaticLaunchCompletion();
}

__global__ void __launch_bounds__(TPB)
hist_kernel(const float4* __restrict__ xs4, const float4* __restrict__ ys4,
            const float* __restrict__ mis, float* __restrict__ out) {
    int i = blockIdx.x * blockDim.x + threadIdx.x;  // one float4 per thread

    // Front-load everything that doesn't touch `out`: runs overlapped with
    // the zero kernel thanks to programmatic dependent launch.
    float mx = __ldg(mis);
    float my = __ldg(mis + 1);
    float4 x4 = xs4[i];
    float4 y4 = ys4[i];

    int   flat[4];
    bool  val[4];
    float px[4] = {x4.x - mx, x4.y - mx, x4.z - mx, x4.w - mx};
    float py[4] = {y4.x - my, y4.y - my, y4.z - my, y4.w - my};
#pragma unroll
    for (int k = 0; k < 4; k++) {
        float x = px[k], y = py[k];
        // Match jnp.floor((x - LEFT)/HSTEP) in fp32, IEEE round-to-nearest division.
        val[k] = (x >= c_LEFT) & (x <= c_RIGHT) & (y >= c_BOTTOM) & (y <= c_TOP);
        int ix = (int)floorf(__fdiv_rn(x - c_LEFT,   c_HSTEP));
        int iy = (int)floorf(__fdiv_rn(y - c_BOTTOM, c_VSTEP));
        if (x == c_RIGHT) ix = NX - 1;
        if (y == c_TOP)   iy = NY - 1;
        ix = min(max(ix, 0), NX - 1);
        iy = min(max(iy, 0), NY - 1);
        flat[k] = (NY - 1 - iy) * NX + ix;
    }

    // Wait for the zero kernel's stores to be visible, then deposit.
    cudaGridDependencySynchronize();

#pragma unroll
    for (int k = 0; k < 4; k++)
        if (val[k]) atomicAdd(out + flat[k], 1.0f);   // RED.E.ADD.F32
}

extern "C" void kernel_launch(void* const* d_in, const int* in_sizes, int n_in,
                              void* d_out, int out_size) {
    const float* xs  = (const float*)d_in[0];
    const float* ys  = (const float*)d_in[1];
    const float* mis = (const float*)d_in[2];
    float* out = (float*)d_out;

    // 1) zero the image
    int n4 = out_size / 4;
    zero_out_kernel<<<(n4 + TPB - 1) / TPB, TPB>>>((float4*)out, n4);

    // 2) histogram, launched as a programmatic dependent of the zero kernel:
    //    its ramp + loads overlap the zero kernel; atomics gated by griddepsync.
    int work = N_PARTICLES / 4;              // 4,194,304 threads
    cudaLaunchConfig_t cfg = {};
    cfg.gridDim  = dim3(work / TPB, 1, 1);
    cfg.blockDim = dim3(TPB, 1, 1);
    cfg.dynamicSmemBytes = 0;
    cfg.stream = 0;
    cudaLaunchAttribute attr[1];
    attr[0].id = cudaLaunchAttributeProgrammaticStreamSerialization;
    attr[0].val.programmaticStreamSerializationAllowed = 1;
    cfg.attrs = attr;
    cfg.numAttrs = 1;
    cudaLaunchKernelEx(&cfg, hist_kernel,
                       (const float4*)xs, (const float4*)ys, mis, out);
}